// round 13
// baseline (speedup 1.0000x reference)
#include <cuda_runtime.h>
#include <math.h>

#define A_TOTAL 8732
#define N_GT    100
#define B_BATCH 64
#define EPSV    1e-6f
#define BA      (B_BATCH * A_TOTAL)
#define BN      (B_BATCH * N_GT)

// Scratch (no allocations allowed -> __device__ globals)
__device__ unsigned long long g_gt_best[BN];  // per (b,n): packed (iou_bits<<32)|(0xFFFFFFFF-a)
__device__ int    g_forced[BA];               // per (b,a): forced gt index (last n wins) or -1
__device__ float  g_best_iou[BA];             // per (b,a): max iou over n (bit-exact)
__device__ int    g_bn[BA];                   // per (b,a): first argmax over n
__device__ float4 g_anc_pre[A_TOTAL];         // {1/w, 1/h, log(w+eps), log(h+eps)}
__device__ float4 g_gt_pre[BN];               // {mcx, mcy, log(mw+eps), log(mh+eps)}

// ---------------- prologue: sentinel init + log/rcp precompute ----------------
__global__ void k_pre(const float4* __restrict__ anchors_cxcywh,
                      const float4* __restrict__ gt_boxes) {
    int i = blockIdx.x * blockDim.x + threadIdx.x;
    if (i < A_TOTAL) {
        float4 an = anchors_cxcywh[i];
        g_anc_pre[i] = make_float4(__fdiv_rn(1.0f, an.z), __fdiv_rn(1.0f, an.w),
                                   logf(an.z + EPSV),     logf(an.w + EPSV));
    }
    int j = i - A_TOTAL;
    if (j >= 0 && j < BN) {
        float4 g = gt_boxes[j];                       // xyxy
        float mw = __fsub_rn(g.z, g.x);
        float mh = __fsub_rn(g.w, g.y);
        g_gt_pre[j] = make_float4(0.5f * __fadd_rn(g.x, g.z),
                                  0.5f * __fadd_rn(g.y, g.w),
                                  logf(mw + EPSV), logf(mh + EPSV));
        g_gt_best[j] = 0xFFFFFFFFull;                 // iou=0, a=0 sentinel
    }
}

// ---------------- main IoU / dual-argmax kernel (branchless, 1 exact div) ----------------
// ALL threads execute the loop (full-warp convergence for __any_sync);
// out-of-range lanes compute a clamped duplicate anchor but are masked out
// of the gt-side candidate set and of all writes.
__global__ void __launch_bounds__(256) k_iou(
    const float4* __restrict__ gt_boxes,      // (B, N, 4) xyxy
    const float4* __restrict__ anchors_xyxy)  // (A, 4)
{
    __shared__ float4 s_gt[N_GT];
    __shared__ float  s_area[N_GT];
    __shared__ unsigned long long s_best[N_GT];

    const int b   = blockIdx.y;
    const int tid = threadIdx.x;

    if (tid < N_GT) {
        float4 g = gt_boxes[b * N_GT + tid];
        s_gt[tid]   = g;
        s_area[tid] = __fmul_rn(__fsub_rn(g.z, g.x), __fsub_rn(g.w, g.y));
        s_best[tid] = 0xFFFFFFFFull;
    }
    __syncthreads();

    const int  a     = blockIdx.x * blockDim.x + tid;
    const bool valid = (a < A_TOTAL);
    const int  a_eff = valid ? a : (A_TOTAL - 1);

    float4 an = anchors_xyxy[a_eff];
    const float Sa = __fmul_rn(__fsub_rn(an.z, an.x), __fsub_rn(an.w, an.y));
    const unsigned int akey = 0xFFFFFFFFu - (unsigned int)a_eff;

    float best = 0.0f;
    int   bn   = 0;

    #pragma unroll 2
    for (int n = 0; n < N_GT; n++) {
        float4 g = s_gt[n];
        float lx = fmaxf(an.x, g.x);
        float ly = fmaxf(an.y, g.y);
        float rx = fminf(an.z, g.z);
        float ry = fminf(an.w, g.w);
        float w  = fmaxf(__fsub_rn(rx, lx), 0.0f);
        float h  = fmaxf(__fsub_rn(ry, ly), 0.0f);
        float inter = __fmul_rn(w, h);
        float u  = __fsub_rn(__fadd_rn(Sa, s_area[n]), inter);
        float iou = __fdiv_rn(inter, u);     // inter==0 -> +0/u = +0, bit-exact

        // anchor-side argmax: strict >, ascending n => first max wins
        if (iou > best) { best = iou; bn = n; }   // FSETP + FSEL + SEL

        // gt-side: warp-uniform broadcast read of current best's hi word,
        // ballot-gated atomic. Stale read is monotone-smaller => only
        // false-positives; iou>0 guard kills the zero-iou storm; !valid
        // lanes never contribute (their anchor is a duplicate).
        float bv = __uint_as_float(
            reinterpret_cast<const unsigned int*>(&s_best[n])[1]);
        bool cand = (iou >= bv) && (iou > 0.0f) && valid;
        if (__any_sync(0xFFFFFFFFu, cand)) {     // full warp converged here
            if (cand) {
                unsigned long long key =
                    ((unsigned long long)__float_as_uint(iou) << 32) | akey;
                atomicMax(&s_best[n], key);
            }
        }
    }
    if (valid) {
        const int o = b * A_TOTAL + a;
        g_best_iou[o] = best;
        g_bn[o]       = bn;
        g_forced[o]   = -1;
    }
    __syncthreads();
    if (tid < N_GT) {
        unsigned long long v = s_best[tid];
        if (v > 0xFFFFFFFFull)
            atomicMax(&g_gt_best[b * N_GT + tid], v);
    }
}

// ---------------- forced-match scatter (last n wins -> atomicMax) ----------------
__global__ void k_assign() {
    int i = blockIdx.x * blockDim.x + threadIdx.x;   // i = b*N + n
    if (i < BN) {
        int b = i / N_GT;
        int n = i - b * N_GT;
        unsigned int abest = 0xFFFFFFFFu - (unsigned int)(g_gt_best[i] & 0xFFFFFFFFull);
        atomicMax(&g_forced[b * A_TOTAL + (int)abest], n);
    }
}

// ---------------- encode epilogue (log-table, no MUFU) ----------------
__global__ void __launch_bounds__(256) k_encode(
    const int*    __restrict__ gt_labels,       // (B, N)
    const float4* __restrict__ anchors_cxcywh,  // (A, 4)
    float* __restrict__ out)
{
    const int a = blockIdx.x * blockDim.x + threadIdx.x;
    if (a >= A_TOTAL) return;
    const int b = blockIdx.y;
    const int i = b * A_TOTAL + a;

    int  f = g_forced[i];
    bool pos;
    int  idx;
    if (f >= 0) { pos = true; idx = f; }
    else        { idx = g_bn[i]; pos = g_best_iou[i] > 0.5f; }   // bit-exact iou

    float4 gp = g_gt_pre[b * N_GT + idx];           // {mcx, mcy, log mw, log mh}
    float4 an = anchors_cxcywh[a];                  // cx, cy, w, h
    float4 ap = g_anc_pre[a];                       // {1/w, 1/h, log w, log h}

    float ecx = __fmul_rn(__fsub_rn(gp.x, an.x), ap.x);
    float ecy = __fmul_rn(__fsub_rn(gp.y, an.y), ap.y);
    float ew  = __fsub_rn(gp.z, ap.z);
    float eh  = __fsub_rn(gp.w, ap.w);

    int lbl = pos ? gt_labels[b * N_GT + idx] : 0;

    // Output layout: [labels (BA)] [encoded (BA*4)] [pos_mask (BA)], all f32
    out[i] = (float)lbl;
    reinterpret_cast<float4*>(out + BA)[i] = make_float4(ecx, ecy, ew, eh);
    out[5 * BA + i] = pos ? 1.0f : 0.0f;
}

extern "C" void kernel_launch(void* const* d_in, const int* in_sizes, int n_in,
                              void* d_out, int out_size)
{
    const int*    gt_labels      = (const int*)   d_in[0];   // (64,100) int32
    const float4* gt_boxes       = (const float4*)d_in[1];   // (64,100,4) f32
    const float4* anchors_cxcywh = (const float4*)d_in[2];   // (8732,4) f32
    const float4* anchors_xyxy   = (const float4*)d_in[3];   // (8732,4) f32
    float*        out            = (float*)d_out;

    k_pre<<<(A_TOTAL + BN + 255) / 256, 256>>>(anchors_cxcywh, gt_boxes);

    dim3 grid1((A_TOTAL + 255) / 256, B_BATCH);
    k_iou<<<grid1, 256>>>(gt_boxes, anchors_xyxy);

    k_assign<<<(BN + 255) / 256, 256>>>();

    dim3 grid2((A_TOTAL + 255) / 256, B_BATCH);
    k_encode<<<grid2, 256>>>(gt_labels, anchors_cxcywh, out);
}

// round 14
// speedup vs baseline: 1.5185x; 1.5185x over previous
#include <cuda_runtime.h>
#include <math.h>

#define A_TOTAL 8732
#define N_GT    100
#define B_BATCH 64
#define EPSV    1e-6f
#define BA      (B_BATCH * A_TOTAL)
#define BN      (B_BATCH * N_GT)

// Scratch (no allocations allowed -> __device__ globals)
__device__ unsigned long long g_gt_best[BN];  // per (b,n): packed (iou_bits<<32)|(0xFFFFFFFF-a)
__device__ int4   g_meta[BA];                 // per (b,a): {forced(-1), bn, iou_bits, 0}
__device__ float4 g_anc_pre[A_TOTAL];         // {1/w, 1/h, log(w+eps), log(h+eps)}
__device__ float4 g_gt_pre[BN];               // {mcx, mcy, log(mw+eps), log(mh+eps)}

// ---------------- prologue: sentinel init + log/rcp precompute ----------------
__global__ void k_pre(const float4* __restrict__ anchors_cxcywh,
                      const float4* __restrict__ gt_boxes) {
    int i = blockIdx.x * blockDim.x + threadIdx.x;
    if (i < A_TOTAL) {
        float4 an = anchors_cxcywh[i];
        g_anc_pre[i] = make_float4(__fdiv_rn(1.0f, an.z), __fdiv_rn(1.0f, an.w),
                                   logf(an.z + EPSV),     logf(an.w + EPSV));
    }
    int j = i - A_TOTAL;
    if (j >= 0 && j < BN) {
        float4 g = gt_boxes[j];                       // xyxy
        float mw = __fsub_rn(g.z, g.x);
        float mh = __fsub_rn(g.w, g.y);
        g_gt_pre[j] = make_float4(0.5f * __fadd_rn(g.x, g.z),
                                  0.5f * __fadd_rn(g.y, g.w),
                                  logf(mw + EPSV), logf(mh + EPSV));
        g_gt_best[j] = 0xFFFFFFFFull;                 // iou=0, a=0 sentinel
    }
}

// ---------------- main IoU / dual-argmax: skip-heavy + warp AABB + 2x tiling ----------------
__global__ void __launch_bounds__(256) k_iou(
    const float4* __restrict__ gt_boxes,      // (B, N, 4) xyxy
    const float4* __restrict__ anchors_xyxy)  // (A, 4)
{
    __shared__ float4 s_gt[N_GT];
    __shared__ float  s_area[N_GT];
    __shared__ unsigned long long s_best[N_GT];

    const int b   = blockIdx.y;
    const int tid = threadIdx.x;

    if (tid < N_GT) {
        float4 g = gt_boxes[b * N_GT + tid];
        s_gt[tid]   = g;
        s_area[tid] = __fmul_rn(__fsub_rn(g.z, g.x), __fsub_rn(g.w, g.y));
        s_best[tid] = 0xFFFFFFFFull;
    }
    __syncthreads();

    const int  a0 = blockIdx.x * 512 + tid;
    const int  a1 = a0 + 256;
    const bool v0 = (a0 < A_TOTAL);
    const bool v1 = (a1 < A_TOTAL);

    float4 an0 = anchors_xyxy[v0 ? a0 : (A_TOTAL - 1)];
    float4 an1 = anchors_xyxy[v1 ? a1 : (A_TOTAL - 1)];
    const float Sa0 = __fmul_rn(__fsub_rn(an0.z, an0.x), __fsub_rn(an0.w, an0.y));
    const float Sa1 = __fmul_rn(__fsub_rn(an1.z, an1.x), __fsub_rn(an1.w, an1.y));
    const unsigned int akey0 = 0xFFFFFFFFu - (unsigned int)a0;
    const unsigned int akey1 = 0xFFFFFFFFu - (unsigned int)a1;

    // Warp-level AABBs (all 256 lanes execute: full warps, no partial-warp UB)
    float l0 = an0.x, t0 = an0.y, r0 = an0.z, d0 = an0.w;
    float l1 = an1.x, t1 = an1.y, r1 = an1.z, d1 = an1.w;
    #pragma unroll
    for (int m = 16; m >= 1; m >>= 1) {
        l0 = fminf(l0, __shfl_xor_sync(0xFFFFFFFFu, l0, m));
        t0 = fminf(t0, __shfl_xor_sync(0xFFFFFFFFu, t0, m));
        r0 = fmaxf(r0, __shfl_xor_sync(0xFFFFFFFFu, r0, m));
        d0 = fmaxf(d0, __shfl_xor_sync(0xFFFFFFFFu, d0, m));
        l1 = fminf(l1, __shfl_xor_sync(0xFFFFFFFFu, l1, m));
        t1 = fminf(t1, __shfl_xor_sync(0xFFFFFFFFu, t1, m));
        r1 = fmaxf(r1, __shfl_xor_sync(0xFFFFFFFFu, r1, m));
        d1 = fmaxf(d1, __shfl_xor_sync(0xFFFFFFFFu, d1, m));
    }

    float best0 = 0.0f, best1 = 0.0f;
    int   bn0 = 0, bn1 = 0;

    const unsigned int* s_best_hi =
        reinterpret_cast<const unsigned int*>(s_best);   // hi word at 2*n+1

    for (int n = 0; n < N_GT; n++) {
        float4 g  = s_gt[n];
        float  ga = s_area[n];

        // ---- group 0: warp-uniform AABB pretest (strict: touching = no area)
        if (g.x < r0 && g.z > l0 && g.y < d0 && g.w > t0) {
            float w = __fsub_rn(fminf(an0.z, g.z), fmaxf(an0.x, g.x));
            float h = __fsub_rn(fminf(an0.w, g.w), fmaxf(an0.y, g.y));
            if (w > 0.0f && h > 0.0f) {                       // per-lane skip
                float inter = __fmul_rn(w, h);
                float u   = __fsub_rn(__fadd_rn(Sa0, ga), inter);
                float iou = __fdiv_rn(inter, u);              // fast path only
                if (iou > best0) { best0 = iou; bn0 = n; }    // first max wins
                // hi-word-only filter: 32-bit read is atomic & monotone,
                // never wrongly skips (>= admits hi-ties for lo tie-break)
                if (v0 && __float_as_uint(iou) >= s_best_hi[2 * n + 1]) {
                    unsigned long long key =
                        ((unsigned long long)__float_as_uint(iou) << 32) | akey0;
                    atomicMax(&s_best[n], key);
                }
            }
        }
        // ---- group 1
        if (g.x < r1 && g.z > l1 && g.y < d1 && g.w > t1) {
            float w = __fsub_rn(fminf(an1.z, g.z), fmaxf(an1.x, g.x));
            float h = __fsub_rn(fminf(an1.w, g.w), fmaxf(an1.y, g.y));
            if (w > 0.0f && h > 0.0f) {
                float inter = __fmul_rn(w, h);
                float u   = __fsub_rn(__fadd_rn(Sa1, ga), inter);
                float iou = __fdiv_rn(inter, u);
                if (iou > best1) { best1 = iou; bn1 = n; }
                if (v1 && __float_as_uint(iou) >= s_best_hi[2 * n + 1]) {
                    unsigned long long key =
                        ((unsigned long long)__float_as_uint(iou) << 32) | akey1;
                    atomicMax(&s_best[n], key);
                }
            }
        }
    }

    if (v0) g_meta[b * A_TOTAL + a0] = make_int4(-1, bn0, __float_as_int(best0), 0);
    if (v1) g_meta[b * A_TOTAL + a1] = make_int4(-1, bn1, __float_as_int(best1), 0);

    __syncthreads();
    if (tid < N_GT) {
        unsigned long long v = s_best[tid];
        if (v > 0xFFFFFFFFull)
            atomicMax(&g_gt_best[b * N_GT + tid], v);
    }
}

// ---------------- forced-match scatter (last n wins -> atomicMax) ----------------
__global__ void k_assign() {
    int i = blockIdx.x * blockDim.x + threadIdx.x;   // i = b*N + n
    if (i < BN) {
        int b = i / N_GT;
        int n = i - b * N_GT;
        unsigned int abest = 0xFFFFFFFFu - (unsigned int)(g_gt_best[i] & 0xFFFFFFFFull);
        atomicMax(&reinterpret_cast<int*>(g_meta)[4 * (b * A_TOTAL + (int)abest)], n);
    }
}

// ---------------- encode epilogue (log-table; 1 LDG.128 metadata) ----------------
__global__ void __launch_bounds__(256) k_encode(
    const int*    __restrict__ gt_labels,       // (B, N)
    const float4* __restrict__ anchors_cxcywh,  // (A, 4)
    float* __restrict__ out)
{
    const int a = blockIdx.x * blockDim.x + threadIdx.x;
    if (a >= A_TOTAL) return;
    const int b = blockIdx.y;
    const int i = b * A_TOTAL + a;

    int4 m = g_meta[i];                              // {forced, bn, iou_bits, -}
    bool pos;
    int  idx;
    if (m.x >= 0) { pos = true; idx = m.x; }
    else          { idx = m.y; pos = __int_as_float(m.z) > 0.5f; }

    float4 gp = g_gt_pre[b * N_GT + idx];            // {mcx, mcy, log mw, log mh}
    float4 an = anchors_cxcywh[a];                   // cx, cy, w, h
    float4 ap = g_anc_pre[a];                        // {1/w, 1/h, log w, log h}

    float ecx = __fmul_rn(__fsub_rn(gp.x, an.x), ap.x);
    float ecy = __fmul_rn(__fsub_rn(gp.y, an.y), ap.y);
    float ew  = __fsub_rn(gp.z, ap.z);
    float eh  = __fsub_rn(gp.w, ap.w);

    int lbl = pos ? gt_labels[b * N_GT + idx] : 0;

    // Output layout: [labels (BA)] [encoded (BA*4)] [pos_mask (BA)], all f32
    out[i] = (float)lbl;
    reinterpret_cast<float4*>(out + BA)[i] = make_float4(ecx, ecy, ew, eh);
    out[5 * BA + i] = pos ? 1.0f : 0.0f;
}

extern "C" void kernel_launch(void* const* d_in, const int* in_sizes, int n_in,
                              void* d_out, int out_size)
{
    const int*    gt_labels      = (const int*)   d_in[0];   // (64,100) int32
    const float4* gt_boxes       = (const float4*)d_in[1];   // (64,100,4) f32
    const float4* anchors_cxcywh = (const float4*)d_in[2];   // (8732,4) f32
    const float4* anchors_xyxy   = (const float4*)d_in[3];   // (8732,4) f32
    float*        out            = (float*)d_out;

    k_pre<<<(A_TOTAL + BN + 255) / 256, 256>>>(anchors_cxcywh, gt_boxes);

    dim3 grid1((A_TOTAL + 511) / 512, B_BATCH);
    k_iou<<<grid1, 256>>>(gt_boxes, anchors_xyxy);

    k_assign<<<(BN + 255) / 256, 256>>>();

    dim3 grid2((A_TOTAL + 255) / 256, B_BATCH);
    k_encode<<<grid2, 256>>>(gt_labels, anchors_cxcywh, out);
}

// round 16
// speedup vs baseline: 1.6446x; 1.0830x over previous
#include <cuda_runtime.h>
#include <math.h>

#define A_TOTAL 8732
#define N_GT    100
#define B_BATCH 64
#define EPSV    1e-6f
#define BA      (B_BATCH * A_TOTAL)
#define BN      (B_BATCH * N_GT)

// Scratch (no allocations allowed -> __device__ globals)
__device__ unsigned long long g_gt_best[BN];  // per (b,n): packed (iou_bits<<32)|(0xFFFFFFFF-a)
__device__ int4   g_meta[BA];                 // per (b,a): {forced(-1), bn, iou_bits, 0}
__device__ float4 g_anc_pre[A_TOTAL];         // {1/w, 1/h, log(w+eps), log(h+eps)}
__device__ float4 g_gt_pre[BN];               // {mcx, mcy, log(mw+eps), log(mh+eps)}

// ---------------- prologue: sentinel init + log/rcp precompute ----------------
__global__ void k_pre(const float4* __restrict__ anchors_cxcywh,
                      const float4* __restrict__ gt_boxes) {
    int i = blockIdx.x * blockDim.x + threadIdx.x;
    if (i < A_TOTAL) {
        float4 an = anchors_cxcywh[i];
        g_anc_pre[i] = make_float4(__fdiv_rn(1.0f, an.z), __fdiv_rn(1.0f, an.w),
                                   logf(an.z + EPSV),     logf(an.w + EPSV));
    }
    int j = i - A_TOTAL;
    if (j >= 0 && j < BN) {
        float4 g = gt_boxes[j];                       // xyxy
        float mw = __fsub_rn(g.z, g.x);
        float mh = __fsub_rn(g.w, g.y);
        g_gt_pre[j] = make_float4(0.5f * __fadd_rn(g.x, g.z),
                                  0.5f * __fadd_rn(g.y, g.w),
                                  logf(mw + EPSV), logf(mh + EPSV));
        g_gt_best[j] = 0xFFFFFFFFull;                 // iou=0, a=0 sentinel
    }
}

// ---------------- main IoU / dual-argmax: per-lane skip + 2x tiling + filtered atomics ----------------
__global__ void __launch_bounds__(256) k_iou(
    const float4* __restrict__ gt_boxes,      // (B, N, 4) xyxy
    const float4* __restrict__ anchors_xyxy)  // (A, 4)
{
    __shared__ float4 s_gt[N_GT];
    __shared__ float  s_area[N_GT];
    __shared__ unsigned long long s_best[N_GT];

    const int b   = blockIdx.y;
    const int tid = threadIdx.x;

    if (tid < N_GT) {
        float4 g = gt_boxes[b * N_GT + tid];
        s_gt[tid]   = g;
        s_area[tid] = __fmul_rn(__fsub_rn(g.z, g.x), __fsub_rn(g.w, g.y));
        s_best[tid] = 0xFFFFFFFFull;
    }
    __syncthreads();

    const int  a0 = blockIdx.x * 512 + tid;
    const int  a1 = a0 + 256;
    const bool v0 = (a0 < A_TOTAL);
    const bool v1 = (a1 < A_TOTAL);

    float4 an0 = anchors_xyxy[v0 ? a0 : (A_TOTAL - 1)];
    float4 an1 = anchors_xyxy[v1 ? a1 : (A_TOTAL - 1)];
    const float Sa0 = __fmul_rn(__fsub_rn(an0.z, an0.x), __fsub_rn(an0.w, an0.y));
    const float Sa1 = __fmul_rn(__fsub_rn(an1.z, an1.x), __fsub_rn(an1.w, an1.y));
    const unsigned int akey0 = 0xFFFFFFFFu - (unsigned int)a0;
    const unsigned int akey1 = 0xFFFFFFFFu - (unsigned int)a1;

    float best0 = 0.0f, best1 = 0.0f;
    int   bn0 = 0, bn1 = 0;

    const unsigned int* s_best_hi =
        reinterpret_cast<const unsigned int*>(s_best);   // hi word at 2*n+1

    for (int n = 0; n < N_GT; n++) {
        float4 g  = s_gt[n];
        float  ga = s_area[n];

        // ---- group 0: per-lane skip (the measured win from v1)
        {
            float w = __fsub_rn(fminf(an0.z, g.z), fmaxf(an0.x, g.x));
            float h = __fsub_rn(fminf(an0.w, g.w), fmaxf(an0.y, g.y));
            if (w > 0.0f && h > 0.0f) {
                float inter = __fmul_rn(w, h);
                float u   = __fsub_rn(__fadd_rn(Sa0, ga), inter);
                float iou = __fdiv_rn(inter, u);              // fast path (inter>0)
                if (iou > best0) { best0 = iou; bn0 = n; }    // first max wins
                // hi-word-only filter: 32-bit read is word-atomic & monotone;
                // >= admits hi-ties so the lo-word tie-break still happens.
                if (v0 && __float_as_uint(iou) >= s_best_hi[2 * n + 1]) {
                    unsigned long long key =
                        ((unsigned long long)__float_as_uint(iou) << 32) | akey0;
                    atomicMax(&s_best[n], key);
                }
            }
        }
        // ---- group 1
        {
            float w = __fsub_rn(fminf(an1.z, g.z), fmaxf(an1.x, g.x));
            float h = __fsub_rn(fminf(an1.w, g.w), fmaxf(an1.y, g.y));
            if (w > 0.0f && h > 0.0f) {
                float inter = __fmul_rn(w, h);
                float u   = __fsub_rn(__fadd_rn(Sa1, ga), inter);
                float iou = __fdiv_rn(inter, u);
                if (iou > best1) { best1 = iou; bn1 = n; }
                if (v1 && __float_as_uint(iou) >= s_best_hi[2 * n + 1]) {
                    unsigned long long key =
                        ((unsigned long long)__float_as_uint(iou) << 32) | akey1;
                    atomicMax(&s_best[n], key);
                }
            }
        }
    }

    if (v0) g_meta[b * A_TOTAL + a0] = make_int4(-1, bn0, __float_as_int(best0), 0);
    if (v1) g_meta[b * A_TOTAL + a1] = make_int4(-1, bn1, __float_as_int(best1), 0);

    __syncthreads();
    if (tid < N_GT) {
        unsigned long long v = s_best[tid];
        if (v > 0xFFFFFFFFull)
            atomicMax(&g_gt_best[b * N_GT + tid], v);
    }
}

// ---------------- forced-match scatter (last n wins -> atomicMax) ----------------
__global__ void k_assign() {
    int i = blockIdx.x * blockDim.x + threadIdx.x;   // i = b*N + n
    if (i < BN) {
        int b = i / N_GT;
        int n = i - b * N_GT;
        unsigned int abest = 0xFFFFFFFFu - (unsigned int)(g_gt_best[i] & 0xFFFFFFFFull);
        atomicMax(&reinterpret_cast<int*>(g_meta)[4 * (b * A_TOTAL + (int)abest)], n);
    }
}

// ---------------- encode epilogue (log-table; 1 LDG.128 metadata) ----------------
__global__ void __launch_bounds__(256) k_encode(
    const int*    __restrict__ gt_labels,       // (B, N)
    const float4* __restrict__ anchors_cxcywh,  // (A, 4)
    float* __restrict__ out)
{
    const int a = blockIdx.x * blockDim.x + threadIdx.x;
    if (a >= A_TOTAL) return;
    const int b = blockIdx.y;
    const int i = b * A_TOTAL + a;

    int4 m = g_meta[i];                              // {forced, bn, iou_bits, -}
    bool pos;
    int  idx;
    if (m.x >= 0) { pos = true; idx = m.x; }
    else          { idx = m.y; pos = __int_as_float(m.z) > 0.5f; }

    float4 gp = g_gt_pre[b * N_GT + idx];            // {mcx, mcy, log mw, log mh}
    float4 an = anchors_cxcywh[a];                   // cx, cy, w, h
    float4 ap = g_anc_pre[a];                        // {1/w, 1/h, log w, log h}

    float ecx = __fmul_rn(__fsub_rn(gp.x, an.x), ap.x);
    float ecy = __fmul_rn(__fsub_rn(gp.y, an.y), ap.y);
    float ew  = __fsub_rn(gp.z, ap.z);
    float eh  = __fsub_rn(gp.w, ap.w);

    int lbl = pos ? gt_labels[b * N_GT + idx] : 0;

    // Output layout: [labels (BA)] [encoded (BA*4)] [pos_mask (BA)], all f32
    out[i] = (float)lbl;
    reinterpret_cast<float4*>(out + BA)[i] = make_float4(ecx, ecy, ew, eh);
    out[5 * BA + i] = pos ? 1.0f : 0.0f;
}

extern "C" void kernel_launch(void* const* d_in, const int* in_sizes, int n_in,
                              void* d_out, int out_size)
{
    const int*    gt_labels      = (const int*)   d_in[0];   // (64,100) int32
    const float4* gt_boxes       = (const float4*)d_in[1];   // (64,100,4) f32
    const float4* anchors_cxcywh = (const float4*)d_in[2];   // (8732,4) f32
    const float4* anchors_xyxy   = (const float4*)d_in[3];   // (8732,4) f32
    float*        out            = (float*)d_out;

    k_pre<<<(A_TOTAL + BN + 255) / 256, 256>>>(anchors_cxcywh, gt_boxes);

    dim3 grid1((A_TOTAL + 511) / 512, B_BATCH);
    k_iou<<<grid1, 256>>>(gt_boxes, anchors_xyxy);

    k_assign<<<(BN + 255) / 256, 256>>>();

    dim3 grid2((A_TOTAL + 255) / 256, B_BATCH);
    k_encode<<<grid2, 256>>>(gt_labels, anchors_cxcywh, out);
}